// round 6
// baseline (speedup 1.0000x reference)
#include <cuda_runtime.h>
#include <cstdint>

// ---------------------------------------------------------------------------
// SPNet, v5: conv+mask kernel (chunked running-max, 64-reg) + sparse paint.
//
// Round-5 lessons:
//  * paint was ALU-bound (192 blind FMAs/thread) -> ffs loop over set bits,
//    float4 palette in smem, ~1 iteration/px typical.
//  * mask at 4.6 TB/s was capped by the 128-reg joint allocation ->
//    running max + incremental tie mask in chunks of 4 loads fits 64 regs
//    (launch_bounds(256,4), 32 warps/SM) without the round-3 spill problem.
// ---------------------------------------------------------------------------

#define BATCH    16
#define HW       160000         // 400*400
#define HW4      40000          // float4 per plane
#define GB_PER_B 157            // ceil(40000/256)
#define NCONVBLK 64
#define NTHREADS 256

__device__ float              g_h1[BATCH * 6  * 64 * 64];
__device__ float              g_h2[BATCH * 12 * 32 * 32];
__device__ float              g_pal[BATCH * 48];
__device__ unsigned long long g_mask[BATCH * HW4];   // 16 bits per px, 4 px per u64
__device__ unsigned           g_flags[48];

__device__ __forceinline__ float leaky(float v) {
    return (v >= 0.f) ? v : 0.01f * v;
}

// ===========================================================================
// Kernel 1: blocks 0..63 conv pipeline, blocks 64.. logit -> tie-mask.
// ===========================================================================
__global__ void __launch_bounds__(NTHREADS, 4)
spnet_mask_kernel(const float* __restrict__ x,
                  const float* __restrict__ logits,
                  const float* __restrict__ w1, const float* __restrict__ b1,
                  const float* __restrict__ w2, const float* __restrict__ b2,
                  const float* __restrict__ w3, const float* __restrict__ b3,
                  const float* __restrict__ w4, const float* __restrict__ b4,
                  const float* __restrict__ w5, const float* __restrict__ b5,
                  const float* __restrict__ w6, const float* __restrict__ b6) {
    const int bid = blockIdx.x;
    const int tid = threadIdx.x;

    // ---------------------------------------------------------------------
    // CONV PATH (b = bid>>2, q = bid&3). May spill under 64-reg cap; fine.
    // ---------------------------------------------------------------------
    if (bid < NCONVBLK) {
        const int b = bid >> 2;
        const int q = bid & 3;

        __shared__ float sw1[162], sb1[6];
        __shared__ float sw2[648], sb2[12];
        __shared__ float sw3[1296], sb3[12];
        __shared__ float sw4[1296], sb4[12];
        __shared__ float sw5[648], sb5[6];
        __shared__ float sw6[18], sb6[3];
        __shared__ float h3[12 * 16 * 16];
        __shared__ float h4[12 * 8 * 8];
        __shared__ float h5[6 * 16];

        for (int i = tid; i < 162; i += NTHREADS) sw1[i] = w1[i];
        for (int i = tid; i < 648; i += NTHREADS) { sw2[i] = w2[i]; sw5[i] = w5[i]; }
        for (int i = tid; i < 1296; i += NTHREADS) { sw3[i] = w3[i]; sw4[i] = w4[i]; }
        if (tid < 18) sw6[tid] = w6[tid];
        if (tid < 12) { sb2[tid] = b2[tid]; sb3[tid] = b3[tid]; sb4[tid] = b4[tid]; }
        if (tid < 6)  { sb1[tid] = b1[tid]; sb5[tid] = b5[tid]; }
        if (tid < 3)  sb6[tid] = b6[tid];
        __syncthreads();

        // conv1, quarter q
        for (int pos = tid; pos < 1024; pos += NTHREADS) {
            const int i = q * 16 + (pos >> 6);
            const int j = pos & 63;
            float acc[6];
#pragma unroll
            for (int oc = 0; oc < 6; oc++) acc[oc] = sb1[oc];
#pragma unroll
            for (int ic = 0; ic < 3; ic++) {
                const float* xp = x + (size_t)(b * 3 + ic) * HW;
#pragma unroll
                for (int di = 0; di < 3; di++) {
                    const int yi = 2 * i + di - 1;
#pragma unroll
                    for (int dj = 0; dj < 3; dj++) {
                        const int yj = 2 * j + dj - 1;
                        float v = 0.f;
                        if (yi >= 0 && yj >= 0) v = xp[yi * 400 + yj];
#pragma unroll
                        for (int oc = 0; oc < 6; oc++)
                            acc[oc] = fmaf(sw1[(oc * 3 + ic) * 9 + di * 3 + dj], v, acc[oc]);
                    }
                }
            }
#pragma unroll
            for (int oc = 0; oc < 6; oc++)
                g_h1[((b * 6 + oc) * 64 + i) * 64 + j] = leaky(acc[oc]);
        }
        __threadfence();
        __syncthreads();
        if (tid == 0) atomicAdd(&g_flags[b], 1u);

        if (tid == 0) {
            while (atomicAdd(&g_flags[b], 0u) < 4u) __nanosleep(64);
            __threadfence();
        }
        __syncthreads();

        // conv2, quarter q
        {
            const int i = q * 8 + (tid >> 5);
            const int j = tid & 31;
            const float* h1b = g_h1 + (size_t)b * 6 * 64 * 64;
            float acc[12];
#pragma unroll
            for (int oc = 0; oc < 12; oc++) acc[oc] = sb2[oc];
#pragma unroll
            for (int ic = 0; ic < 6; ic++) {
#pragma unroll
                for (int di = 0; di < 3; di++) {
                    const int yi = 2 * i + di - 1;
#pragma unroll
                    for (int dj = 0; dj < 3; dj++) {
                        const int yj = 2 * j + dj - 1;
                        float v = 0.f;
                        if (yi >= 0 && yj >= 0) v = h1b[(ic * 64 + yi) * 64 + yj];
#pragma unroll
                        for (int oc = 0; oc < 12; oc++)
                            acc[oc] = fmaf(sw2[(oc * 6 + ic) * 9 + di * 3 + dj], v, acc[oc]);
                    }
                }
            }
#pragma unroll
            for (int oc = 0; oc < 12; oc++)
                g_h2[((b * 12 + oc) * 32 + i) * 32 + j] = leaky(acc[oc]);
        }
        __threadfence();
        __syncthreads();
        if (tid == 0) atomicAdd(&g_flags[16 + b], 1u);

        if (q != 0) return;

        if (tid == 0) {
            while (atomicAdd(&g_flags[16 + b], 0u) < 4u) __nanosleep(64);
            __threadfence();
        }
        __syncthreads();

        // conv3
        {
            const int i = tid >> 4;
            const int j = tid & 15;
            const float* h2b = g_h2 + (size_t)b * 12 * 32 * 32;
            float acc[12];
#pragma unroll
            for (int oc = 0; oc < 12; oc++) acc[oc] = sb3[oc];
            for (int ic = 0; ic < 12; ic++) {
#pragma unroll
                for (int di = 0; di < 3; di++) {
                    const int yi = 2 * i + di - 1;
#pragma unroll
                    for (int dj = 0; dj < 3; dj++) {
                        const int yj = 2 * j + dj - 1;
                        float v = 0.f;
                        if (yi >= 0 && yj >= 0) v = h2b[(ic * 32 + yi) * 32 + yj];
#pragma unroll
                        for (int oc = 0; oc < 12; oc++)
                            acc[oc] = fmaf(sw3[(oc * 12 + ic) * 9 + di * 3 + dj], v, acc[oc]);
                    }
                }
            }
#pragma unroll
            for (int oc = 0; oc < 12; oc++)
                h3[(oc * 16 + i) * 16 + j] = leaky(acc[oc]);
        }
        __syncthreads();

        // conv4
        if (tid < 64) {
            const int i = tid >> 3;
            const int j = tid & 7;
            float acc[12];
#pragma unroll
            for (int oc = 0; oc < 12; oc++) acc[oc] = sb4[oc];
            for (int ic = 0; ic < 12; ic++) {
#pragma unroll
                for (int di = 0; di < 3; di++) {
                    const int yi = 2 * i + di - 1;
#pragma unroll
                    for (int dj = 0; dj < 3; dj++) {
                        const int yj = 2 * j + dj - 1;
                        float v = 0.f;
                        if (yi >= 0 && yj >= 0) v = h3[(ic * 16 + yi) * 16 + yj];
#pragma unroll
                        for (int oc = 0; oc < 12; oc++)
                            acc[oc] = fmaf(sw4[(oc * 12 + ic) * 9 + di * 3 + dj], v, acc[oc]);
                    }
                }
            }
#pragma unroll
            for (int oc = 0; oc < 12; oc++)
                h4[(oc * 8 + i) * 8 + j] = leaky(acc[oc]);
        }
        __syncthreads();

        // conv5
        if (tid < 96) {
            const int oc = tid >> 4;
            const int p  = tid & 15;
            const int i  = p >> 2;
            const int jj = p & 3;
            float acc = sb5[oc];
            for (int ic = 0; ic < 12; ic++) {
#pragma unroll
                for (int di = 0; di < 3; di++) {
                    const int yi = 2 * i + di - 1;
#pragma unroll
                    for (int dj = 0; dj < 3; dj++) {
                        const int yj = 2 * jj + dj - 1;
                        float v = 0.f;
                        if (yi >= 0 && yj >= 0) v = h4[(ic * 8 + yi) * 8 + yj];
                        acc = fmaf(sw5[(oc * 12 + ic) * 9 + di * 3 + dj], v, acc);
                    }
                }
            }
            h5[oc * 16 + p] = leaky(acc);
        }
        __syncthreads();

        // conv6 (1x1) + relu -> g_pal (paint kernel is stream-ordered)
        if (tid < 48) {
            const int c = tid >> 4;
            const int k = tid & 15;
            float acc = sb6[c];
#pragma unroll
            for (int ic = 0; ic < 6; ic++)
                acc = fmaf(sw6[c * 6 + ic], h5[ic * 16 + k], acc);
            g_pal[b * 48 + c * 16 + k] = fmaxf(acc, 0.f);
        }
        return;
    }

    // ---------------------------------------------------------------------
    // MASK PATH: running max + incremental tie mask, 4-load chunks.
    // Mask reset on strictly-greater, OR on equal == compare-to-final-max.
    // ---------------------------------------------------------------------
    const int gid = bid - NCONVBLK;
    const int b   = gid / GB_PER_B;
    const int blk = gid - b * GB_PER_B;
    const int p   = blk * NTHREADS + tid;
    if (p >= HW4) return;

    const float4* lg = reinterpret_cast<const float4*>(logits)
                       + (size_t)b * 16 * HW4 + p;

    float4 mx = make_float4(-__FLT_MAX__, -__FLT_MAX__, -__FLT_MAX__, -__FLT_MAX__);
    unsigned mA = 0, mB = 0, mC = 0, mD = 0;

#pragma unroll
    for (int c = 0; c < 4; c++) {
        float4 l[4];
#pragma unroll
        for (int t = 0; t < 4; t++)
            l[t] = __ldcs(lg + (size_t)(c * 4 + t) * HW4);

#pragma unroll
        for (int t = 0; t < 4; t++) {
            const unsigned bit = 1u << (c * 4 + t);
            // x lane
            mA = (l[t].x > mx.x) ? bit : ((l[t].x == mx.x) ? (mA | bit) : mA);
            mx.x = fmaxf(mx.x, l[t].x);
            // y lane
            mB = (l[t].y > mx.y) ? bit : ((l[t].y == mx.y) ? (mB | bit) : mB);
            mx.y = fmaxf(mx.y, l[t].y);
            // z lane
            mC = (l[t].z > mx.z) ? bit : ((l[t].z == mx.z) ? (mC | bit) : mC);
            mx.z = fmaxf(mx.z, l[t].z);
            // w lane
            mD = (l[t].w > mx.w) ? bit : ((l[t].w == mx.w) ? (mD | bit) : mD);
            mx.w = fmaxf(mx.w, l[t].w);
        }
    }

    const unsigned long long m =
        (unsigned long long)mA
        | ((unsigned long long)mB << 16)
        | ((unsigned long long)mC << 32)
        | ((unsigned long long)mD << 48);
    g_mask[(size_t)b * HW4 + p] = m;
}

// ===========================================================================
// Kernel 2: paint. Sparse ffs loop over tie mask (typically 1 bit set).
// ===========================================================================
__global__ void __launch_bounds__(NTHREADS)
spnet_paint_kernel(float* __restrict__ out) {
    const int gid = blockIdx.x;
    const int b   = gid / GB_PER_B;
    const int blk = gid - b * GB_PER_B;
    const int p   = blk * NTHREADS + threadIdx.x;

    __shared__ float4 spal4[16];
    if (threadIdx.x < 16) {
        const int k = threadIdx.x;
        spal4[k] = make_float4(g_pal[b * 48 + k],
                               g_pal[b * 48 + 16 + k],
                               g_pal[b * 48 + 32 + k],
                               0.f);
    }
    __syncthreads();

    if (p >= HW4) return;

    const unsigned long long m = g_mask[(size_t)b * HW4 + p];

    float r0[4], r1[4], r2[4];
#pragma unroll
    for (int px = 0; px < 4; px++) {
        unsigned bits = (unsigned)((m >> (16 * px)) & 0xFFFFull);
        float s0 = 0.f, s1 = 0.f, s2 = 0.f;
        // typically exactly one bit set; loop handles ties exactly
        while (bits) {
            const int k = __ffs(bits) - 1;
            bits &= bits - 1;
            const float4 c = spal4[k];
            s0 += c.x; s1 += c.y; s2 += c.z;
        }
        r0[px] = s0; r1[px] = s1; r2[px] = s2;
    }

    float4* o = reinterpret_cast<float4*>(out) + (size_t)(b * 3) * HW4 + p;
    o[0]               = make_float4(r0[0], r0[1], r0[2], r0[3]);
    o[HW4]             = make_float4(r1[0], r1[1], r1[2], r1[3]);
    o[2 * (size_t)HW4] = make_float4(r2[0], r2[1], r2[2], r2[3]);
}

// ---------------------------------------------------------------------------
extern "C" void kernel_launch(void* const* d_in, const int* in_sizes, int n_in,
                              void* d_out, int out_size) {
    (void)in_sizes; (void)n_in; (void)out_size;
    const float* x  = (const float*)d_in[0];
    const float* bl = (const float*)d_in[1];
    const float* w1 = (const float*)d_in[2];
    const float* b1 = (const float*)d_in[3];
    const float* w2 = (const float*)d_in[4];
    const float* b2 = (const float*)d_in[5];
    const float* w3 = (const float*)d_in[6];
    const float* b3 = (const float*)d_in[7];
    const float* w4 = (const float*)d_in[8];
    const float* b4 = (const float*)d_in[9];
    const float* w5 = (const float*)d_in[10];
    const float* b5 = (const float*)d_in[11];
    const float* w6 = (const float*)d_in[12];
    const float* b6 = (const float*)d_in[13];
    float* out = (float*)d_out;

    void* flags_ptr = nullptr;
    cudaGetSymbolAddress(&flags_ptr, g_flags);
    cudaMemsetAsync(flags_ptr, 0, 48 * sizeof(unsigned));

    spnet_mask_kernel<<<NCONVBLK + BATCH * GB_PER_B, NTHREADS>>>(
        x, bl, w1, b1, w2, b2, w3, b3, w4, b4, w5, b5, w6, b6);
    spnet_paint_kernel<<<BATCH * GB_PER_B, NTHREADS>>>(out);
}

// round 7
// speedup vs baseline: 1.0264x; 1.0264x over previous
#include <cuda_runtime.h>
#include <cstdint>

// ---------------------------------------------------------------------------
// SPNet, v6: best-of-both recombination.
//   Mask kernel  = round-5 shape: conv blocks (128-reg, no spill) + mask path
//                  with 16-wide front-batched float4 loads (proven 5.6 TB/s
//                  operating point from round 1), plain loads.
//   Paint kernel = round-6 ffs sparse loop (10.8 us, ALU-light).
// Round-6 lesson: chunked running-max halved per-SM MLP (32w x 4 < 16w x 16)
// and the 64-reg cap spilled the conv path; both reverted.
// ---------------------------------------------------------------------------

#define BATCH    16
#define HW       160000         // 400*400
#define HW4      40000          // float4 per plane
#define GB_PER_B 157            // ceil(40000/256)
#define NCONVBLK 64
#define NTHREADS 256

__device__ float              g_h1[BATCH * 6  * 64 * 64];
__device__ float              g_h2[BATCH * 12 * 32 * 32];
__device__ float              g_pal[BATCH * 48];
__device__ unsigned long long g_mask[BATCH * HW4];   // 16 bits/px, 4 px per u64
__device__ unsigned           g_flags[48];

__device__ __forceinline__ float leaky(float v) {
    return (v >= 0.f) ? v : 0.01f * v;
}

// ===========================================================================
// Kernel 1: blocks 0..63 conv pipeline, blocks 64.. logit -> tie-mask.
// ===========================================================================
__global__ void __launch_bounds__(NTHREADS, 2)
spnet_mask_kernel(const float* __restrict__ x,
                  const float* __restrict__ logits,
                  const float* __restrict__ w1, const float* __restrict__ b1,
                  const float* __restrict__ w2, const float* __restrict__ b2,
                  const float* __restrict__ w3, const float* __restrict__ b3,
                  const float* __restrict__ w4, const float* __restrict__ b4,
                  const float* __restrict__ w5, const float* __restrict__ b5,
                  const float* __restrict__ w6, const float* __restrict__ b6) {
    const int bid = blockIdx.x;
    const int tid = threadIdx.x;

    // ---------------------------------------------------------------------
    // CONV PATH (b = bid>>2, q = bid&3) — 128-reg conditions, no spills.
    // ---------------------------------------------------------------------
    if (bid < NCONVBLK) {
        const int b = bid >> 2;
        const int q = bid & 3;

        __shared__ float sw1[162], sb1[6];
        __shared__ float sw2[648], sb2[12];
        __shared__ float sw3[1296], sb3[12];
        __shared__ float sw4[1296], sb4[12];
        __shared__ float sw5[648], sb5[6];
        __shared__ float sw6[18], sb6[3];
        __shared__ float h3[12 * 16 * 16];
        __shared__ float h4[12 * 8 * 8];
        __shared__ float h5[6 * 16];

        for (int i = tid; i < 162; i += NTHREADS) sw1[i] = w1[i];
        for (int i = tid; i < 648; i += NTHREADS) { sw2[i] = w2[i]; sw5[i] = w5[i]; }
        for (int i = tid; i < 1296; i += NTHREADS) { sw3[i] = w3[i]; sw4[i] = w4[i]; }
        if (tid < 18) sw6[tid] = w6[tid];
        if (tid < 12) { sb2[tid] = b2[tid]; sb3[tid] = b3[tid]; sb4[tid] = b4[tid]; }
        if (tid < 6)  { sb1[tid] = b1[tid]; sb5[tid] = b5[tid]; }
        if (tid < 3)  sb6[tid] = b6[tid];
        __syncthreads();

        // conv1, quarter q
        for (int pos = tid; pos < 1024; pos += NTHREADS) {
            const int i = q * 16 + (pos >> 6);
            const int j = pos & 63;
            float acc[6];
#pragma unroll
            for (int oc = 0; oc < 6; oc++) acc[oc] = sb1[oc];
#pragma unroll
            for (int ic = 0; ic < 3; ic++) {
                const float* xp = x + (size_t)(b * 3 + ic) * HW;
#pragma unroll
                for (int di = 0; di < 3; di++) {
                    const int yi = 2 * i + di - 1;
#pragma unroll
                    for (int dj = 0; dj < 3; dj++) {
                        const int yj = 2 * j + dj - 1;
                        float v = 0.f;
                        if (yi >= 0 && yj >= 0) v = xp[yi * 400 + yj];
#pragma unroll
                        for (int oc = 0; oc < 6; oc++)
                            acc[oc] = fmaf(sw1[(oc * 3 + ic) * 9 + di * 3 + dj], v, acc[oc]);
                    }
                }
            }
#pragma unroll
            for (int oc = 0; oc < 6; oc++)
                g_h1[((b * 6 + oc) * 64 + i) * 64 + j] = leaky(acc[oc]);
        }
        __threadfence();
        __syncthreads();
        if (tid == 0) atomicAdd(&g_flags[b], 1u);

        if (tid == 0) {
            while (atomicAdd(&g_flags[b], 0u) < 4u) __nanosleep(64);
            __threadfence();
        }
        __syncthreads();

        // conv2, quarter q
        {
            const int i = q * 8 + (tid >> 5);
            const int j = tid & 31;
            const float* h1b = g_h1 + (size_t)b * 6 * 64 * 64;
            float acc[12];
#pragma unroll
            for (int oc = 0; oc < 12; oc++) acc[oc] = sb2[oc];
#pragma unroll
            for (int ic = 0; ic < 6; ic++) {
#pragma unroll
                for (int di = 0; di < 3; di++) {
                    const int yi = 2 * i + di - 1;
#pragma unroll
                    for (int dj = 0; dj < 3; dj++) {
                        const int yj = 2 * j + dj - 1;
                        float v = 0.f;
                        if (yi >= 0 && yj >= 0) v = h1b[(ic * 64 + yi) * 64 + yj];
#pragma unroll
                        for (int oc = 0; oc < 12; oc++)
                            acc[oc] = fmaf(sw2[(oc * 6 + ic) * 9 + di * 3 + dj], v, acc[oc]);
                    }
                }
            }
#pragma unroll
            for (int oc = 0; oc < 12; oc++)
                g_h2[((b * 12 + oc) * 32 + i) * 32 + j] = leaky(acc[oc]);
        }
        __threadfence();
        __syncthreads();
        if (tid == 0) atomicAdd(&g_flags[16 + b], 1u);

        if (q != 0) return;

        if (tid == 0) {
            while (atomicAdd(&g_flags[16 + b], 0u) < 4u) __nanosleep(64);
            __threadfence();
        }
        __syncthreads();

        // conv3
        {
            const int i = tid >> 4;
            const int j = tid & 15;
            const float* h2b = g_h2 + (size_t)b * 12 * 32 * 32;
            float acc[12];
#pragma unroll
            for (int oc = 0; oc < 12; oc++) acc[oc] = sb3[oc];
            for (int ic = 0; ic < 12; ic++) {
#pragma unroll
                for (int di = 0; di < 3; di++) {
                    const int yi = 2 * i + di - 1;
#pragma unroll
                    for (int dj = 0; dj < 3; dj++) {
                        const int yj = 2 * j + dj - 1;
                        float v = 0.f;
                        if (yi >= 0 && yj >= 0) v = h2b[(ic * 32 + yi) * 32 + yj];
#pragma unroll
                        for (int oc = 0; oc < 12; oc++)
                            acc[oc] = fmaf(sw3[(oc * 12 + ic) * 9 + di * 3 + dj], v, acc[oc]);
                    }
                }
            }
#pragma unroll
            for (int oc = 0; oc < 12; oc++)
                h3[(oc * 16 + i) * 16 + j] = leaky(acc[oc]);
        }
        __syncthreads();

        // conv4
        if (tid < 64) {
            const int i = tid >> 3;
            const int j = tid & 7;
            float acc[12];
#pragma unroll
            for (int oc = 0; oc < 12; oc++) acc[oc] = sb4[oc];
            for (int ic = 0; ic < 12; ic++) {
#pragma unroll
                for (int di = 0; di < 3; di++) {
                    const int yi = 2 * i + di - 1;
#pragma unroll
                    for (int dj = 0; dj < 3; dj++) {
                        const int yj = 2 * j + dj - 1;
                        float v = 0.f;
                        if (yi >= 0 && yj >= 0) v = h3[(ic * 16 + yi) * 16 + yj];
#pragma unroll
                        for (int oc = 0; oc < 12; oc++)
                            acc[oc] = fmaf(sw4[(oc * 12 + ic) * 9 + di * 3 + dj], v, acc[oc]);
                    }
                }
            }
#pragma unroll
            for (int oc = 0; oc < 12; oc++)
                h4[(oc * 8 + i) * 8 + j] = leaky(acc[oc]);
        }
        __syncthreads();

        // conv5
        if (tid < 96) {
            const int oc = tid >> 4;
            const int p  = tid & 15;
            const int i  = p >> 2;
            const int jj = p & 3;
            float acc = sb5[oc];
            for (int ic = 0; ic < 12; ic++) {
#pragma unroll
                for (int di = 0; di < 3; di++) {
                    const int yi = 2 * i + di - 1;
#pragma unroll
                    for (int dj = 0; dj < 3; dj++) {
                        const int yj = 2 * jj + dj - 1;
                        float v = 0.f;
                        if (yi >= 0 && yj >= 0) v = h4[(ic * 8 + yi) * 8 + yj];
                        acc = fmaf(sw5[(oc * 12 + ic) * 9 + di * 3 + dj], v, acc);
                    }
                }
            }
            h5[oc * 16 + p] = leaky(acc);
        }
        __syncthreads();

        // conv6 (1x1) + relu -> g_pal (paint kernel is stream-ordered)
        if (tid < 48) {
            const int c = tid >> 4;
            const int k = tid & 15;
            float acc = sb6[c];
#pragma unroll
            for (int ic = 0; ic < 6; ic++)
                acc = fmaf(sw6[c * 6 + ic], h5[ic * 16 + k], acc);
            g_pal[b * 48 + c * 16 + k] = fmaxf(acc, 0.f);
        }
        return;
    }

    // ---------------------------------------------------------------------
    // MASK PATH: 16-wide front-batched float4 loads (round-1 operating
    // point), then max, then tie bitmask. Plain loads, streaming store.
    // ---------------------------------------------------------------------
    const int gid = bid - NCONVBLK;
    const int b   = gid / GB_PER_B;
    const int blk = gid - b * GB_PER_B;
    const int p   = blk * NTHREADS + tid;
    if (p >= HW4) return;

    const float4* lg = reinterpret_cast<const float4*>(logits)
                       + (size_t)b * 16 * HW4 + p;

    float4 l[16];
#pragma unroll
    for (int k = 0; k < 16; k++) l[k] = lg[(size_t)k * HW4];

    float4 mx = l[0];
#pragma unroll
    for (int k = 1; k < 16; k++) {
        mx.x = fmaxf(mx.x, l[k].x);
        mx.y = fmaxf(mx.y, l[k].y);
        mx.z = fmaxf(mx.z, l[k].z);
        mx.w = fmaxf(mx.w, l[k].w);
    }

    unsigned mA = 0, mB = 0, mC = 0, mD = 0;
#pragma unroll
    for (int k = 0; k < 16; k++) {
        mA |= (l[k].x == mx.x) ? (1u << k) : 0u;
        mB |= (l[k].y == mx.y) ? (1u << k) : 0u;
        mC |= (l[k].z == mx.z) ? (1u << k) : 0u;
        mD |= (l[k].w == mx.w) ? (1u << k) : 0u;
    }

    const unsigned long long m =
        (unsigned long long)mA
        | ((unsigned long long)mB << 16)
        | ((unsigned long long)mC << 32)
        | ((unsigned long long)mD << 48);
    __stcs(&g_mask[(size_t)b * HW4 + p], m);
}

// ===========================================================================
// Kernel 2: paint. Sparse ffs loop over tie mask (typically 1 bit set).
// ===========================================================================
__global__ void __launch_bounds__(NTHREADS)
spnet_paint_kernel(float* __restrict__ out) {
    const int gid = blockIdx.x;
    const int b   = gid / GB_PER_B;
    const int blk = gid - b * GB_PER_B;
    const int p   = blk * NTHREADS + threadIdx.x;

    __shared__ float4 spal4[16];
    if (threadIdx.x < 16) {
        const int k = threadIdx.x;
        spal4[k] = make_float4(g_pal[b * 48 + k],
                               g_pal[b * 48 + 16 + k],
                               g_pal[b * 48 + 32 + k],
                               0.f);
    }
    __syncthreads();

    if (p >= HW4) return;

    const unsigned long long m = __ldcg(&g_mask[(size_t)b * HW4 + p]);

    float r0[4], r1[4], r2[4];
#pragma unroll
    for (int px = 0; px < 4; px++) {
        unsigned bits = (unsigned)((m >> (16 * px)) & 0xFFFFull);
        float s0 = 0.f, s1 = 0.f, s2 = 0.f;
        while (bits) {
            const int k = __ffs(bits) - 1;
            bits &= bits - 1;
            const float4 c = spal4[k];
            s0 += c.x; s1 += c.y; s2 += c.z;
        }
        r0[px] = s0; r1[px] = s1; r2[px] = s2;
    }

    float4* o = reinterpret_cast<float4*>(out) + (size_t)(b * 3) * HW4 + p;
    o[0]               = make_float4(r0[0], r0[1], r0[2], r0[3]);
    o[HW4]             = make_float4(r1[0], r1[1], r1[2], r1[3]);
    o[2 * (size_t)HW4] = make_float4(r2[0], r2[1], r2[2], r2[3]);
}

// ---------------------------------------------------------------------------
extern "C" void kernel_launch(void* const* d_in, const int* in_sizes, int n_in,
                              void* d_out, int out_size) {
    (void)in_sizes; (void)n_in; (void)out_size;
    const float* x  = (const float*)d_in[0];
    const float* bl = (const float*)d_in[1];
    const float* w1 = (const float*)d_in[2];
    const float* b1 = (const float*)d_in[3];
    const float* w2 = (const float*)d_in[4];
    const float* b2 = (const float*)d_in[5];
    const float* w3 = (const float*)d_in[6];
    const float* b3 = (const float*)d_in[7];
    const float* w4 = (const float*)d_in[8];
    const float* b4 = (const float*)d_in[9];
    const float* w5 = (const float*)d_in[10];
    const float* b5 = (const float*)d_in[11];
    const float* w6 = (const float*)d_in[12];
    const float* b6 = (const float*)d_in[13];
    float* out = (float*)d_out;

    void* flags_ptr = nullptr;
    cudaGetSymbolAddress(&flags_ptr, g_flags);
    cudaMemsetAsync(flags_ptr, 0, 48 * sizeof(unsigned));

    spnet_mask_kernel<<<NCONVBLK + BATCH * GB_PER_B, NTHREADS>>>(
        x, bl, w1, b1, w2, b2, w3, b3, w4, b4, w5, b5, w6, b6);
    spnet_paint_kernel<<<BATCH * GB_PER_B, NTHREADS>>>(out);
}

// round 8
// speedup vs baseline: 1.2383x; 1.2065x over previous
#include <cuda_runtime.h>
#include <cstdint>

// ---------------------------------------------------------------------------
// SPNet, v7.
//   Mask kernel  = exact round-5 mask path (the 37.5us measurement):
//                  __ldcs 16-wide front-batched float4 loads, PLAIN mask
//                  store, launch_bounds(256,2), conv blocks 0..63.
//                  Round-7 lesson: dropping __ldcs cost ~11us (L2 thrash).
//   Paint kernel = ffs sparse loop, now 8 px/thread (ulonglong2 mask load,
//                  2x float4 stores per channel).
// ---------------------------------------------------------------------------

#define BATCH    16
#define HW       160000         // 400*400
#define HW4      40000          // float4 per plane
#define HW8      20000          // ulonglong2 mask entries per image
#define GB_PER_B 157            // ceil(40000/256)  (mask kernel)
#define PB_PER_B 79             // ceil(20000/256)  (paint kernel)
#define NCONVBLK 64
#define NTHREADS 256

__device__ float              g_h1[BATCH * 6  * 64 * 64];
__device__ float              g_h2[BATCH * 12 * 32 * 32];
__device__ float              g_pal[BATCH * 48];
__device__ unsigned long long g_mask[BATCH * HW4];   // 16 bits/px, 4 px per u64
__device__ unsigned           g_flags[48];

__device__ __forceinline__ float leaky(float v) {
    return (v >= 0.f) ? v : 0.01f * v;
}

// ===========================================================================
// Kernel 1: blocks 0..63 conv pipeline, blocks 64.. logit -> tie-mask.
// ===========================================================================
__global__ void __launch_bounds__(NTHREADS, 2)
spnet_mask_kernel(const float* __restrict__ x,
                  const float* __restrict__ logits,
                  const float* __restrict__ w1, const float* __restrict__ b1,
                  const float* __restrict__ w2, const float* __restrict__ b2,
                  const float* __restrict__ w3, const float* __restrict__ b3,
                  const float* __restrict__ w4, const float* __restrict__ b4,
                  const float* __restrict__ w5, const float* __restrict__ b5,
                  const float* __restrict__ w6, const float* __restrict__ b6) {
    const int bid = blockIdx.x;
    const int tid = threadIdx.x;

    // ---------------------------------------------------------------------
    // CONV PATH (b = bid>>2, q = bid&3).
    // ---------------------------------------------------------------------
    if (bid < NCONVBLK) {
        const int b = bid >> 2;
        const int q = bid & 3;

        __shared__ float sw1[162], sb1[6];
        __shared__ float sw2[648], sb2[12];
        __shared__ float sw3[1296], sb3[12];
        __shared__ float sw4[1296], sb4[12];
        __shared__ float sw5[648], sb5[6];
        __shared__ float sw6[18], sb6[3];
        __shared__ float h3[12 * 16 * 16];
        __shared__ float h4[12 * 8 * 8];
        __shared__ float h5[6 * 16];

        for (int i = tid; i < 162; i += NTHREADS) sw1[i] = w1[i];
        for (int i = tid; i < 648; i += NTHREADS) { sw2[i] = w2[i]; sw5[i] = w5[i]; }
        for (int i = tid; i < 1296; i += NTHREADS) { sw3[i] = w3[i]; sw4[i] = w4[i]; }
        if (tid < 18) sw6[tid] = w6[tid];
        if (tid < 12) { sb2[tid] = b2[tid]; sb3[tid] = b3[tid]; sb4[tid] = b4[tid]; }
        if (tid < 6)  { sb1[tid] = b1[tid]; sb5[tid] = b5[tid]; }
        if (tid < 3)  sb6[tid] = b6[tid];
        __syncthreads();

        // conv1, quarter q
        for (int pos = tid; pos < 1024; pos += NTHREADS) {
            const int i = q * 16 + (pos >> 6);
            const int j = pos & 63;
            float acc[6];
#pragma unroll
            for (int oc = 0; oc < 6; oc++) acc[oc] = sb1[oc];
#pragma unroll
            for (int ic = 0; ic < 3; ic++) {
                const float* xp = x + (size_t)(b * 3 + ic) * HW;
#pragma unroll
                for (int di = 0; di < 3; di++) {
                    const int yi = 2 * i + di - 1;
#pragma unroll
                    for (int dj = 0; dj < 3; dj++) {
                        const int yj = 2 * j + dj - 1;
                        float v = 0.f;
                        if (yi >= 0 && yj >= 0) v = xp[yi * 400 + yj];
#pragma unroll
                        for (int oc = 0; oc < 6; oc++)
                            acc[oc] = fmaf(sw1[(oc * 3 + ic) * 9 + di * 3 + dj], v, acc[oc]);
                    }
                }
            }
#pragma unroll
            for (int oc = 0; oc < 6; oc++)
                g_h1[((b * 6 + oc) * 64 + i) * 64 + j] = leaky(acc[oc]);
        }
        __threadfence();
        __syncthreads();
        if (tid == 0) atomicAdd(&g_flags[b], 1u);

        if (tid == 0) {
            while (atomicAdd(&g_flags[b], 0u) < 4u) __nanosleep(64);
            __threadfence();
        }
        __syncthreads();

        // conv2, quarter q
        {
            const int i = q * 8 + (tid >> 5);
            const int j = tid & 31;
            const float* h1b = g_h1 + (size_t)b * 6 * 64 * 64;
            float acc[12];
#pragma unroll
            for (int oc = 0; oc < 12; oc++) acc[oc] = sb2[oc];
#pragma unroll
            for (int ic = 0; ic < 6; ic++) {
#pragma unroll
                for (int di = 0; di < 3; di++) {
                    const int yi = 2 * i + di - 1;
#pragma unroll
                    for (int dj = 0; dj < 3; dj++) {
                        const int yj = 2 * j + dj - 1;
                        float v = 0.f;
                        if (yi >= 0 && yj >= 0) v = h1b[(ic * 64 + yi) * 64 + yj];
#pragma unroll
                        for (int oc = 0; oc < 12; oc++)
                            acc[oc] = fmaf(sw2[(oc * 6 + ic) * 9 + di * 3 + dj], v, acc[oc]);
                    }
                }
            }
#pragma unroll
            for (int oc = 0; oc < 12; oc++)
                g_h2[((b * 12 + oc) * 32 + i) * 32 + j] = leaky(acc[oc]);
        }
        __threadfence();
        __syncthreads();
        if (tid == 0) atomicAdd(&g_flags[16 + b], 1u);

        if (q != 0) return;

        if (tid == 0) {
            while (atomicAdd(&g_flags[16 + b], 0u) < 4u) __nanosleep(64);
            __threadfence();
        }
        __syncthreads();

        // conv3
        {
            const int i = tid >> 4;
            const int j = tid & 15;
            const float* h2b = g_h2 + (size_t)b * 12 * 32 * 32;
            float acc[12];
#pragma unroll
            for (int oc = 0; oc < 12; oc++) acc[oc] = sb3[oc];
            for (int ic = 0; ic < 12; ic++) {
#pragma unroll
                for (int di = 0; di < 3; di++) {
                    const int yi = 2 * i + di - 1;
#pragma unroll
                    for (int dj = 0; dj < 3; dj++) {
                        const int yj = 2 * j + dj - 1;
                        float v = 0.f;
                        if (yi >= 0 && yj >= 0) v = h2b[(ic * 32 + yi) * 32 + yj];
#pragma unroll
                        for (int oc = 0; oc < 12; oc++)
                            acc[oc] = fmaf(sw3[(oc * 12 + ic) * 9 + di * 3 + dj], v, acc[oc]);
                    }
                }
            }
#pragma unroll
            for (int oc = 0; oc < 12; oc++)
                h3[(oc * 16 + i) * 16 + j] = leaky(acc[oc]);
        }
        __syncthreads();

        // conv4
        if (tid < 64) {
            const int i = tid >> 3;
            const int j = tid & 7;
            float acc[12];
#pragma unroll
            for (int oc = 0; oc < 12; oc++) acc[oc] = sb4[oc];
            for (int ic = 0; ic < 12; ic++) {
#pragma unroll
                for (int di = 0; di < 3; di++) {
                    const int yi = 2 * i + di - 1;
#pragma unroll
                    for (int dj = 0; dj < 3; dj++) {
                        const int yj = 2 * j + dj - 1;
                        float v = 0.f;
                        if (yi >= 0 && yj >= 0) v = h3[(ic * 16 + yi) * 16 + yj];
#pragma unroll
                        for (int oc = 0; oc < 12; oc++)
                            acc[oc] = fmaf(sw4[(oc * 12 + ic) * 9 + di * 3 + dj], v, acc[oc]);
                    }
                }
            }
#pragma unroll
            for (int oc = 0; oc < 12; oc++)
                h4[(oc * 8 + i) * 8 + j] = leaky(acc[oc]);
        }
        __syncthreads();

        // conv5
        if (tid < 96) {
            const int oc = tid >> 4;
            const int p  = tid & 15;
            const int i  = p >> 2;
            const int jj = p & 3;
            float acc = sb5[oc];
            for (int ic = 0; ic < 12; ic++) {
#pragma unroll
                for (int di = 0; di < 3; di++) {
                    const int yi = 2 * i + di - 1;
#pragma unroll
                    for (int dj = 0; dj < 3; dj++) {
                        const int yj = 2 * jj + dj - 1;
                        float v = 0.f;
                        if (yi >= 0 && yj >= 0) v = h4[(ic * 8 + yi) * 8 + yj];
                        acc = fmaf(sw5[(oc * 12 + ic) * 9 + di * 3 + dj], v, acc);
                    }
                }
            }
            h5[oc * 16 + p] = leaky(acc);
        }
        __syncthreads();

        // conv6 (1x1) + relu -> g_pal (paint kernel is stream-ordered)
        if (tid < 48) {
            const int c = tid >> 4;
            const int k = tid & 15;
            float acc = sb6[c];
#pragma unroll
            for (int ic = 0; ic < 6; ic++)
                acc = fmaf(sw6[c * 6 + ic], h5[ic * 16 + k], acc);
            g_pal[b * 48 + c * 16 + k] = fmaxf(acc, 0.f);
        }
        return;
    }

    // ---------------------------------------------------------------------
    // MASK PATH (exact round-5 code): __ldcs front batch, plain store.
    // ---------------------------------------------------------------------
    const int gid = bid - NCONVBLK;
    const int b   = gid / GB_PER_B;
    const int blk = gid - b * GB_PER_B;
    const int p   = blk * NTHREADS + tid;
    if (p >= HW4) return;

    const float4* lg = reinterpret_cast<const float4*>(logits)
                       + (size_t)b * 16 * HW4 + p;

    float4 l[16];
#pragma unroll
    for (int k = 0; k < 16; k++) l[k] = __ldcs(lg + (size_t)k * HW4);

    float4 mx = l[0];
#pragma unroll
    for (int k = 1; k < 16; k++) {
        mx.x = fmaxf(mx.x, l[k].x);
        mx.y = fmaxf(mx.y, l[k].y);
        mx.z = fmaxf(mx.z, l[k].z);
        mx.w = fmaxf(mx.w, l[k].w);
    }

    unsigned mA = 0, mB = 0, mC = 0, mD = 0;
#pragma unroll
    for (int k = 0; k < 16; k++) {
        mA |= (l[k].x == mx.x) ? (1u << k) : 0u;
        mB |= (l[k].y == mx.y) ? (1u << k) : 0u;
        mC |= (l[k].z == mx.z) ? (1u << k) : 0u;
        mD |= (l[k].w == mx.w) ? (1u << k) : 0u;
    }

    const unsigned long long m =
        (unsigned long long)mA
        | ((unsigned long long)mB << 16)
        | ((unsigned long long)mC << 32)
        | ((unsigned long long)mD << 48);
    g_mask[(size_t)b * HW4 + p] = m;
}

// ===========================================================================
// Kernel 2: paint, 8 px per thread (ulonglong2 mask load).
// ===========================================================================
__global__ void __launch_bounds__(NTHREADS)
spnet_paint_kernel(float* __restrict__ out) {
    const int gid = blockIdx.x;
    const int b   = gid / PB_PER_B;
    const int blk = gid - b * PB_PER_B;
    const int p2  = blk * NTHREADS + threadIdx.x;   // ulonglong2 index

    __shared__ float4 spal4[16];
    if (threadIdx.x < 16) {
        const int k = threadIdx.x;
        spal4[k] = make_float4(g_pal[b * 48 + k],
                               g_pal[b * 48 + 16 + k],
                               g_pal[b * 48 + 32 + k],
                               0.f);
    }
    __syncthreads();

    if (p2 >= HW8) return;

    const ulonglong2 mm = reinterpret_cast<const ulonglong2*>(g_mask)[(size_t)b * HW8 + p2];

    float r0[8], r1[8], r2[8];
#pragma unroll
    for (int half = 0; half < 2; half++) {
        const unsigned long long m = half ? mm.y : mm.x;
#pragma unroll
        for (int px = 0; px < 4; px++) {
            unsigned bits = (unsigned)((m >> (16 * px)) & 0xFFFFull);
            float s0 = 0.f, s1 = 0.f, s2 = 0.f;
            while (bits) {
                const int k = __ffs(bits) - 1;
                bits &= bits - 1;
                const float4 c = spal4[k];
                s0 += c.x; s1 += c.y; s2 += c.z;
            }
            const int o = half * 4 + px;
            r0[o] = s0; r1[o] = s1; r2[o] = s2;
        }
    }

    float4* o = reinterpret_cast<float4*>(out) + (size_t)(b * 3) * HW4 + 2 * p2;
#pragma unroll
    for (int half = 0; half < 2; half++) {
        o[half]                     = make_float4(r0[half*4], r0[half*4+1], r0[half*4+2], r0[half*4+3]);
        o[HW4 + half]               = make_float4(r1[half*4], r1[half*4+1], r1[half*4+2], r1[half*4+3]);
        o[2 * (size_t)HW4 + half]   = make_float4(r2[half*4], r2[half*4+1], r2[half*4+2], r2[half*4+3]);
    }
}

// ---------------------------------------------------------------------------
extern "C" void kernel_launch(void* const* d_in, const int* in_sizes, int n_in,
                              void* d_out, int out_size) {
    (void)in_sizes; (void)n_in; (void)out_size;
    const float* x  = (const float*)d_in[0];
    const float* bl = (const float*)d_in[1];
    const float* w1 = (const float*)d_in[2];
    const float* b1 = (const float*)d_in[3];
    const float* w2 = (const float*)d_in[4];
    const float* b2 = (const float*)d_in[5];
    const float* w3 = (const float*)d_in[6];
    const float* b3 = (const float*)d_in[7];
    const float* w4 = (const float*)d_in[8];
    const float* b4 = (const float*)d_in[9];
    const float* w5 = (const float*)d_in[10];
    const float* b5 = (const float*)d_in[11];
    const float* w6 = (const float*)d_in[12];
    const float* b6 = (const float*)d_in[13];
    float* out = (float*)d_out;

    void* flags_ptr = nullptr;
    cudaGetSymbolAddress(&flags_ptr, g_flags);
    cudaMemsetAsync(flags_ptr, 0, 48 * sizeof(unsigned));

    spnet_mask_kernel<<<NCONVBLK + BATCH * GB_PER_B, NTHREADS>>>(
        x, bl, w1, b1, w2, b2, w3, b3, w4, b4, w5, b5, w6, b6);
    spnet_paint_kernel<<<BATCH * PB_PER_B, NTHREADS>>>(out);
}

// round 9
// speedup vs baseline: 1.2472x; 1.0072x over previous
#include <cuda_runtime.h>
#include <cstdint>

// ---------------------------------------------------------------------------
// SPNet, v8: hybrid direct-paint.
//   Mask kernel: conv blocks 0..63 publish palette -> flag. Gather blocks
//   issue all 16 logit loads (__ldcs), then NON-BLOCKING check of the
//   palette flag: if set (all waves after ~6us), paint output directly and
//   skip the mask write; else write tie-mask + per-block need flag.
//   Paint kernel: early-exits for already-painted blocks (most of them),
//   paints the remainder (round-6 4px ffs shape; the 8px variant regressed
//   due to local-memory indexed arrays).
// Output values identical on both paths -> deterministic d_out.
// ---------------------------------------------------------------------------

#define BATCH    16
#define HW       160000         // 400*400
#define HW4      40000          // float4 per plane
#define GB_PER_B 157            // ceil(40000/256)
#define NGATHER  (BATCH * GB_PER_B)   // 2512
#define NCONVBLK 64
#define NTHREADS 256

__device__ float              g_h1[BATCH * 6  * 64 * 64];
__device__ float              g_h2[BATCH * 12 * 32 * 32];
__device__ float              g_pal[BATCH * 48];
__device__ unsigned long long g_mask[BATCH * HW4];
// g_sync[0:16) conv1 count, [16:32) conv2 count, [32:48) pal-ready,
// g_sync[48 .. 48+NGATHER) per-gather-block "needs paint" flag.
__device__ unsigned           g_sync[48 + NGATHER];

__device__ __forceinline__ float leaky(float v) {
    return (v >= 0.f) ? v : 0.01f * v;
}

// ===========================================================================
// Kernel 1: blocks 0..63 conv pipeline, blocks 64.. logit -> mask OR paint.
// ===========================================================================
__global__ void __launch_bounds__(NTHREADS, 2)
spnet_mask_kernel(const float* __restrict__ x,
                  const float* __restrict__ logits,
                  const float* __restrict__ w1, const float* __restrict__ b1,
                  const float* __restrict__ w2, const float* __restrict__ b2,
                  const float* __restrict__ w3, const float* __restrict__ b3,
                  const float* __restrict__ w4, const float* __restrict__ b4,
                  const float* __restrict__ w5, const float* __restrict__ b5,
                  const float* __restrict__ w6, const float* __restrict__ b6,
                  float* __restrict__ out) {
    const int bid = blockIdx.x;
    const int tid = threadIdx.x;

    // ---------------------------------------------------------------------
    // CONV PATH (b = bid>>2, q = bid&3).
    // ---------------------------------------------------------------------
    if (bid < NCONVBLK) {
        const int b = bid >> 2;
        const int q = bid & 3;

        __shared__ float sw1[162], sb1[6];
        __shared__ float sw2[648], sb2[12];
        __shared__ float sw3[1296], sb3[12];
        __shared__ float sw4[1296], sb4[12];
        __shared__ float sw5[648], sb5[6];
        __shared__ float sw6[18], sb6[3];
        __shared__ float h3[12 * 16 * 16];
        __shared__ float h4[12 * 8 * 8];
        __shared__ float h5[6 * 16];

        for (int i = tid; i < 162; i += NTHREADS) sw1[i] = w1[i];
        for (int i = tid; i < 648; i += NTHREADS) { sw2[i] = w2[i]; sw5[i] = w5[i]; }
        for (int i = tid; i < 1296; i += NTHREADS) { sw3[i] = w3[i]; sw4[i] = w4[i]; }
        if (tid < 18) sw6[tid] = w6[tid];
        if (tid < 12) { sb2[tid] = b2[tid]; sb3[tid] = b3[tid]; sb4[tid] = b4[tid]; }
        if (tid < 6)  { sb1[tid] = b1[tid]; sb5[tid] = b5[tid]; }
        if (tid < 3)  sb6[tid] = b6[tid];
        __syncthreads();

        // conv1, quarter q
        for (int pos = tid; pos < 1024; pos += NTHREADS) {
            const int i = q * 16 + (pos >> 6);
            const int j = pos & 63;
            float acc[6];
#pragma unroll
            for (int oc = 0; oc < 6; oc++) acc[oc] = sb1[oc];
#pragma unroll
            for (int ic = 0; ic < 3; ic++) {
                const float* xp = x + (size_t)(b * 3 + ic) * HW;
#pragma unroll
                for (int di = 0; di < 3; di++) {
                    const int yi = 2 * i + di - 1;
#pragma unroll
                    for (int dj = 0; dj < 3; dj++) {
                        const int yj = 2 * j + dj - 1;
                        float v = 0.f;
                        if (yi >= 0 && yj >= 0) v = xp[yi * 400 + yj];
#pragma unroll
                        for (int oc = 0; oc < 6; oc++)
                            acc[oc] = fmaf(sw1[(oc * 3 + ic) * 9 + di * 3 + dj], v, acc[oc]);
                    }
                }
            }
#pragma unroll
            for (int oc = 0; oc < 6; oc++)
                g_h1[((b * 6 + oc) * 64 + i) * 64 + j] = leaky(acc[oc]);
        }
        __threadfence();
        __syncthreads();
        if (tid == 0) atomicAdd(&g_sync[b], 1u);

        if (tid == 0) {
            while (atomicAdd(&g_sync[b], 0u) < 4u) __nanosleep(64);
            __threadfence();
        }
        __syncthreads();

        // conv2, quarter q
        {
            const int i = q * 8 + (tid >> 5);
            const int j = tid & 31;
            const float* h1b = g_h1 + (size_t)b * 6 * 64 * 64;
            float acc[12];
#pragma unroll
            for (int oc = 0; oc < 12; oc++) acc[oc] = sb2[oc];
#pragma unroll
            for (int ic = 0; ic < 6; ic++) {
#pragma unroll
                for (int di = 0; di < 3; di++) {
                    const int yi = 2 * i + di - 1;
#pragma unroll
                    for (int dj = 0; dj < 3; dj++) {
                        const int yj = 2 * j + dj - 1;
                        float v = 0.f;
                        if (yi >= 0 && yj >= 0) v = h1b[(ic * 64 + yi) * 64 + yj];
#pragma unroll
                        for (int oc = 0; oc < 12; oc++)
                            acc[oc] = fmaf(sw2[(oc * 6 + ic) * 9 + di * 3 + dj], v, acc[oc]);
                    }
                }
            }
#pragma unroll
            for (int oc = 0; oc < 12; oc++)
                g_h2[((b * 12 + oc) * 32 + i) * 32 + j] = leaky(acc[oc]);
        }
        __threadfence();
        __syncthreads();
        if (tid == 0) atomicAdd(&g_sync[16 + b], 1u);

        if (q != 0) return;

        if (tid == 0) {
            while (atomicAdd(&g_sync[16 + b], 0u) < 4u) __nanosleep(64);
            __threadfence();
        }
        __syncthreads();

        // conv3
        {
            const int i = tid >> 4;
            const int j = tid & 15;
            const float* h2b = g_h2 + (size_t)b * 12 * 32 * 32;
            float acc[12];
#pragma unroll
            for (int oc = 0; oc < 12; oc++) acc[oc] = sb3[oc];
            for (int ic = 0; ic < 12; ic++) {
#pragma unroll
                for (int di = 0; di < 3; di++) {
                    const int yi = 2 * i + di - 1;
#pragma unroll
                    for (int dj = 0; dj < 3; dj++) {
                        const int yj = 2 * j + dj - 1;
                        float v = 0.f;
                        if (yi >= 0 && yj >= 0) v = h2b[(ic * 32 + yi) * 32 + yj];
#pragma unroll
                        for (int oc = 0; oc < 12; oc++)
                            acc[oc] = fmaf(sw3[(oc * 12 + ic) * 9 + di * 3 + dj], v, acc[oc]);
                    }
                }
            }
#pragma unroll
            for (int oc = 0; oc < 12; oc++)
                h3[(oc * 16 + i) * 16 + j] = leaky(acc[oc]);
        }
        __syncthreads();

        // conv4
        if (tid < 64) {
            const int i = tid >> 3;
            const int j = tid & 7;
            float acc[12];
#pragma unroll
            for (int oc = 0; oc < 12; oc++) acc[oc] = sb4[oc];
            for (int ic = 0; ic < 12; ic++) {
#pragma unroll
                for (int di = 0; di < 3; di++) {
                    const int yi = 2 * i + di - 1;
#pragma unroll
                    for (int dj = 0; dj < 3; dj++) {
                        const int yj = 2 * j + dj - 1;
                        float v = 0.f;
                        if (yi >= 0 && yj >= 0) v = h3[(ic * 16 + yi) * 16 + yj];
#pragma unroll
                        for (int oc = 0; oc < 12; oc++)
                            acc[oc] = fmaf(sw4[(oc * 12 + ic) * 9 + di * 3 + dj], v, acc[oc]);
                    }
                }
            }
#pragma unroll
            for (int oc = 0; oc < 12; oc++)
                h4[(oc * 8 + i) * 8 + j] = leaky(acc[oc]);
        }
        __syncthreads();

        // conv5
        if (tid < 96) {
            const int oc = tid >> 4;
            const int p  = tid & 15;
            const int i  = p >> 2;
            const int jj = p & 3;
            float acc = sb5[oc];
            for (int ic = 0; ic < 12; ic++) {
#pragma unroll
                for (int di = 0; di < 3; di++) {
                    const int yi = 2 * i + di - 1;
#pragma unroll
                    for (int dj = 0; dj < 3; dj++) {
                        const int yj = 2 * jj + dj - 1;
                        float v = 0.f;
                        if (yi >= 0 && yj >= 0) v = h4[(ic * 8 + yi) * 8 + yj];
                        acc = fmaf(sw5[(oc * 12 + ic) * 9 + di * 3 + dj], v, acc);
                    }
                }
            }
            h5[oc * 16 + p] = leaky(acc);
        }
        __syncthreads();

        // conv6 (1x1) + relu -> g_pal, then publish pal-ready flag
        if (tid < 48) {
            const int c = tid >> 4;
            const int k = tid & 15;
            float acc = sb6[c];
#pragma unroll
            for (int ic = 0; ic < 6; ic++)
                acc = fmaf(sw6[c * 6 + ic], h5[ic * 16 + k], acc);
            g_pal[b * 48 + c * 16 + k] = fmaxf(acc, 0.f);
            __threadfence();
        }
        __syncthreads();
        if (tid == 0) atomicExch(&g_sync[32 + b], 1u);
        return;
    }

    // ---------------------------------------------------------------------
    // GATHER PATH: loads first (MLP), then non-blocking palette-flag check.
    // ---------------------------------------------------------------------
    const int gid = bid - NCONVBLK;
    const int b   = gid / GB_PER_B;
    const int blk = gid - b * GB_PER_B;
    const int p   = blk * NTHREADS + tid;
    const bool act = (p < HW4);

    __shared__ float4   spal4[16];
    __shared__ unsigned s_ready;

    float4 l[16];
    if (act) {
        const float4* lg = reinterpret_cast<const float4*>(logits)
                           + (size_t)b * 16 * HW4 + p;
#pragma unroll
        for (int k = 0; k < 16; k++) l[k] = __ldcs(lg + (size_t)k * HW4);
    }

    // non-blocking check: palette ready? (set for all waves after ~6us)
    if (tid == 0) {
        const unsigned r = atomicAdd(&g_sync[32 + b], 0u);
        if (r) __threadfence();
        s_ready = r;
    }
    __syncthreads();
    const bool direct = (s_ready != 0u);
    if (direct && tid < 16) {
        const int k = tid;
        spal4[k] = make_float4(__ldcg(&g_pal[b * 48 + k]),
                               __ldcg(&g_pal[b * 48 + 16 + k]),
                               __ldcg(&g_pal[b * 48 + 32 + k]),
                               0.f);
    }
    __syncthreads();

    if (!act) return;

    float4 mx = l[0];
#pragma unroll
    for (int k = 1; k < 16; k++) {
        mx.x = fmaxf(mx.x, l[k].x);
        mx.y = fmaxf(mx.y, l[k].y);
        mx.z = fmaxf(mx.z, l[k].z);
        mx.w = fmaxf(mx.w, l[k].w);
    }

    unsigned mA = 0, mB = 0, mC = 0, mD = 0;
#pragma unroll
    for (int k = 0; k < 16; k++) {
        mA |= (l[k].x == mx.x) ? (1u << k) : 0u;
        mB |= (l[k].y == mx.y) ? (1u << k) : 0u;
        mC |= (l[k].z == mx.z) ? (1u << k) : 0u;
        mD |= (l[k].w == mx.w) ? (1u << k) : 0u;
    }

    if (direct) {
        // paint inline
        float r0[4], r1[4], r2[4];
        unsigned ms[4] = { mA, mB, mC, mD };
#pragma unroll
        for (int px = 0; px < 4; px++) {
            unsigned bits = ms[px];
            float s0 = 0.f, s1 = 0.f, s2 = 0.f;
            while (bits) {
                const int k = __ffs(bits) - 1;
                bits &= bits - 1;
                const float4 c = spal4[k];
                s0 += c.x; s1 += c.y; s2 += c.z;
            }
            r0[px] = s0; r1[px] = s1; r2[px] = s2;
        }
        float4* o = reinterpret_cast<float4*>(out) + (size_t)(b * 3) * HW4 + p;
        __stcs(o,                    make_float4(r0[0], r0[1], r0[2], r0[3]));
        __stcs(o + HW4,              make_float4(r1[0], r1[1], r1[2], r1[3]));
        __stcs(o + 2 * (size_t)HW4,  make_float4(r2[0], r2[1], r2[2], r2[3]));
    } else {
        const unsigned long long m =
            (unsigned long long)mA
            | ((unsigned long long)mB << 16)
            | ((unsigned long long)mC << 32)
            | ((unsigned long long)mD << 48);
        g_mask[(size_t)b * HW4 + p] = m;
        if (tid == 0) g_sync[48 + gid] = 1u;   // needs paint
    }
}

// ===========================================================================
// Kernel 2: paint leftovers (blocks whose gather ran before palette ready).
// ===========================================================================
__global__ void __launch_bounds__(NTHREADS)
spnet_paint_kernel(float* __restrict__ out) {
    const int gid = blockIdx.x;

    __shared__ unsigned s_need;
    if (threadIdx.x == 0) s_need = g_sync[48 + gid];
    __syncthreads();
    if (!s_need) return;   // already painted inline

    const int b   = gid / GB_PER_B;
    const int blk = gid - b * GB_PER_B;
    const int p   = blk * NTHREADS + threadIdx.x;

    __shared__ float4 spal4[16];
    if (threadIdx.x < 16) {
        const int k = threadIdx.x;
        spal4[k] = make_float4(g_pal[b * 48 + k],
                               g_pal[b * 48 + 16 + k],
                               g_pal[b * 48 + 32 + k],
                               0.f);
    }
    __syncthreads();

    if (p >= HW4) return;

    const unsigned long long m = g_mask[(size_t)b * HW4 + p];

    float r0[4], r1[4], r2[4];
#pragma unroll
    for (int px = 0; px < 4; px++) {
        unsigned bits = (unsigned)((m >> (16 * px)) & 0xFFFFull);
        float s0 = 0.f, s1 = 0.f, s2 = 0.f;
        while (bits) {
            const int k = __ffs(bits) - 1;
            bits &= bits - 1;
            const float4 c = spal4[k];
            s0 += c.x; s1 += c.y; s2 += c.z;
        }
        r0[px] = s0; r1[px] = s1; r2[px] = s2;
    }

    float4* o = reinterpret_cast<float4*>(out) + (size_t)(b * 3) * HW4 + p;
    o[0]               = make_float4(r0[0], r0[1], r0[2], r0[3]);
    o[HW4]             = make_float4(r1[0], r1[1], r1[2], r1[3]);
    o[2 * (size_t)HW4] = make_float4(r2[0], r2[1], r2[2], r2[3]);
}

// ---------------------------------------------------------------------------
extern "C" void kernel_launch(void* const* d_in, const int* in_sizes, int n_in,
                              void* d_out, int out_size) {
    (void)in_sizes; (void)n_in; (void)out_size;
    const float* x  = (const float*)d_in[0];
    const float* bl = (const float*)d_in[1];
    const float* w1 = (const float*)d_in[2];
    const float* b1 = (const float*)d_in[3];
    const float* w2 = (const float*)d_in[4];
    const float* b2 = (const float*)d_in[5];
    const float* w3 = (const float*)d_in[6];
    const float* b3 = (const float*)d_in[7];
    const float* w4 = (const float*)d_in[8];
    const float* b4 = (const float*)d_in[9];
    const float* w5 = (const float*)d_in[10];
    const float* b5 = (const float*)d_in[11];
    const float* w6 = (const float*)d_in[12];
    const float* b6 = (const float*)d_in[13];
    float* out = (float*)d_out;

    void* sync_ptr = nullptr;
    cudaGetSymbolAddress(&sync_ptr, g_sync);
    cudaMemsetAsync(sync_ptr, 0, (48 + NGATHER) * sizeof(unsigned));

    spnet_mask_kernel<<<NCONVBLK + NGATHER, NTHREADS>>>(
        x, bl, w1, b1, w2, b2, w3, b3, w4, b4, w5, b5, w6, b6, out);
    spnet_paint_kernel<<<NGATHER, NTHREADS>>>(out);
}